// round 1
// baseline (speedup 1.0000x reference)
#include <cuda_runtime.h>
#include <cstdint>

// Problem constants
#define NR   16384
#define DIN  1024
#define DH   4096
#define DZ   256
#define KCB  4096

// ---------------- scratch (device globals; no allocations allowed) ----------
__device__ float g_h1[NR * DH];        // 256 MB
__device__ float g_h2[NR * DH];        // 256 MB
__device__ float g_z [NR * DZ];        // 16 MB
__device__ float g_znorm[NR];
__device__ float g_cnorm[KCB];
__device__ float g_pval[4 * NR];
__device__ int   g_pidx[4 * NR];
__device__ float g_minval[NR];
__device__ int   g_minidx[NR];

// ---------------- fp32 SGEMM:  C = act(A[M,K] @ B[K,N] + bias) --------------
// 128x128 block tile, BK=16, 256 threads, 8x8 register microtile,
// global->register prefetch to hide HBM latency.
template<bool RELU>
__global__ __launch_bounds__(256)
void sgemm_bias_kernel(const float* __restrict__ A, const float* __restrict__ B,
                       const float* __restrict__ bias, float* __restrict__ C,
                       int M, int Nc, int Kd)
{
    const int BM = 128, BN = 128, BK = 16;
    __shared__ float As[BK][BM];   // transposed A tile
    __shared__ float Bs[BK][BN];

    const int tid = threadIdx.x;
    const int tm = tid >> 4;          // 0..15
    const int tn = tid & 15;          // 0..15
    const int bm = blockIdx.y;
    const int bn = blockIdx.x;

    const float* Ablk = A + (size_t)bm * BM * Kd;
    const float* Bblk = B + (size_t)bn * BN;

    // A tile: 128 rows x 16 cols = 512 float4; each thread loads 2.
    const int a_row = tid >> 2;            // 0..63  (second: +64)
    const int a_col = (tid & 3) * 4;       // 0,4,8,12
    // B tile: 16 rows x 128 cols = 512 float4; each thread loads 2.
    const int b_row = tid >> 5;            // 0..7   (second: +8)
    const int b_col = (tid & 31) * 4;      // 0..124

    float acc[8][8];
#pragma unroll
    for (int i = 0; i < 8; i++)
#pragma unroll
        for (int j = 0; j < 8; j++) acc[i][j] = 0.f;

    float4 pa0, pa1, pb0, pb1;
    pa0 = *(const float4*)(Ablk + (size_t)a_row        * Kd + a_col);
    pa1 = *(const float4*)(Ablk + (size_t)(a_row + 64) * Kd + a_col);
    pb0 = *(const float4*)(Bblk + (size_t)b_row        * Nc + b_col);
    pb1 = *(const float4*)(Bblk + (size_t)(b_row + 8)  * Nc + b_col);

    for (int k0 = 0; k0 < Kd; k0 += BK) {
        // store current tile into smem (A transposed)
        As[a_col + 0][a_row]      = pa0.x;
        As[a_col + 1][a_row]      = pa0.y;
        As[a_col + 2][a_row]      = pa0.z;
        As[a_col + 3][a_row]      = pa0.w;
        As[a_col + 0][a_row + 64] = pa1.x;
        As[a_col + 1][a_row + 64] = pa1.y;
        As[a_col + 2][a_row + 64] = pa1.z;
        As[a_col + 3][a_row + 64] = pa1.w;
        *(float4*)&Bs[b_row][b_col]     = pb0;
        *(float4*)&Bs[b_row + 8][b_col] = pb1;
        __syncthreads();

        // prefetch next tile
        if (k0 + BK < Kd) {
            const int kn = k0 + BK;
            pa0 = *(const float4*)(Ablk + (size_t)a_row        * Kd + kn + a_col);
            pa1 = *(const float4*)(Ablk + (size_t)(a_row + 64) * Kd + kn + a_col);
            pb0 = *(const float4*)(Bblk + (size_t)(kn + b_row)     * Nc + b_col);
            pb1 = *(const float4*)(Bblk + (size_t)(kn + b_row + 8) * Nc + b_col);
        }

#pragma unroll
        for (int kk = 0; kk < BK; kk++) {
            float a[8], b[8];
            *(float4*)&a[0] = *(const float4*)&As[kk][tm * 8];
            *(float4*)&a[4] = *(const float4*)&As[kk][tm * 8 + 4];
            *(float4*)&b[0] = *(const float4*)&Bs[kk][tn * 8];
            *(float4*)&b[4] = *(const float4*)&Bs[kk][tn * 8 + 4];
#pragma unroll
            for (int i = 0; i < 8; i++)
#pragma unroll
                for (int j = 0; j < 8; j++) acc[i][j] += a[i] * b[j];
        }
        __syncthreads();
    }

    // epilogue: bias (+relu), vectorized stores
    const int row0 = bm * BM + tm * 8;
    const int col0 = bn * BN + tn * 8;
    float bv[8];
    *(float4*)&bv[0] = *(const float4*)&bias[col0];
    *(float4*)&bv[4] = *(const float4*)&bias[col0 + 4];
#pragma unroll
    for (int i = 0; i < 8; i++) {
        float v[8];
#pragma unroll
        for (int j = 0; j < 8; j++) {
            float t = acc[i][j] + bv[j];
            if (RELU) t = t > 0.f ? t : 0.f;
            v[j] = t;
        }
        float* crow = C + (size_t)(row0 + i) * Nc + col0;
        *(float4*)&crow[0] = *(float4*)&v[0];
        *(float4*)&crow[4] = *(float4*)&v[4];
    }
}

// ---------------- row squared norms, 256 columns -----------------------------
__global__ void rownorm256_kernel(const float* __restrict__ X, float* __restrict__ out, int rows)
{
    int gw   = (blockIdx.x * blockDim.x + threadIdx.x) >> 5;
    int lane = threadIdx.x & 31;
    if (gw >= rows) return;
    const float* row = X + (size_t)gw * 256;
    float s = 0.f;
    for (int c = lane * 4; c < 256; c += 128) {
        float4 v = *(const float4*)&row[c];
        s += v.x * v.x + v.y * v.y + v.z * v.z + v.w * v.w;
    }
#pragma unroll
    for (int o = 16; o; o >>= 1) s += __shfl_xor_sync(0xffffffffu, s, o);
    if (!lane) out[gw] = s;
}

// ---------------- fused distance-GEMM + running argmin -----------------------
// score(i,j) = cnorm[j] - 2*(z_i . c_j); znorm added later (row-constant).
// grid: (4 j-groups of 1024, 128 row-tiles of 128). NT layout (both row-major,
// K=256 contraction).
__global__ __launch_bounds__(256)
void distmin_kernel(const float* __restrict__ Z, const float* __restrict__ CB,
                    const float* __restrict__ cnorm,
                    float* __restrict__ pval, int* __restrict__ pidx)
{
    const int BM = 128, BN = 128, BK = 16, KD = 256, JG = 1024;
    __shared__ float As[BK][BM];
    __shared__ float Bs[BK][BN];
    __shared__ float s_rv[BM][17];
    __shared__ int   s_ri[BM][17];
    __shared__ float s_bestv[BM];
    __shared__ int   s_besti[BM];

    const int tid = threadIdx.x;
    const int tm = tid >> 4, tn = tid & 15;
    const int bm  = blockIdx.y;
    const int grp = blockIdx.x;

    if (tid < BM) { s_bestv[tid] = 3.4e38f; s_besti[tid] = 0; }

    const float* Ablk = Z + (size_t)bm * BM * KD;
    const int t_row = tid >> 2;           // 0..63 (+64)
    const int t_col = (tid & 3) * 4;      // k-offset within tile

    for (int j0 = grp * JG; j0 < grp * JG + JG; j0 += BN) {
        const float* Bblk = CB + (size_t)j0 * KD;   // 128 codebook rows x 256
        float acc[8][8];
#pragma unroll
        for (int i = 0; i < 8; i++)
#pragma unroll
            for (int j = 0; j < 8; j++) acc[i][j] = 0.f;

        float4 pa0, pa1, pb0, pb1;
        pa0 = *(const float4*)(Ablk + (size_t)t_row        * KD + t_col);
        pa1 = *(const float4*)(Ablk + (size_t)(t_row + 64) * KD + t_col);
        pb0 = *(const float4*)(Bblk + (size_t)t_row        * KD + t_col);
        pb1 = *(const float4*)(Bblk + (size_t)(t_row + 64) * KD + t_col);

        for (int k0 = 0; k0 < KD; k0 += BK) {
            __syncthreads();    // guard smem reuse (prev compute / prev tiles)
            As[t_col + 0][t_row]      = pa0.x;
            As[t_col + 1][t_row]      = pa0.y;
            As[t_col + 2][t_row]      = pa0.z;
            As[t_col + 3][t_row]      = pa0.w;
            As[t_col + 0][t_row + 64] = pa1.x;
            As[t_col + 1][t_row + 64] = pa1.y;
            As[t_col + 2][t_row + 64] = pa1.z;
            As[t_col + 3][t_row + 64] = pa1.w;
            Bs[t_col + 0][t_row]      = pb0.x;
            Bs[t_col + 1][t_row]      = pb0.y;
            Bs[t_col + 2][t_row]      = pb0.z;
            Bs[t_col + 3][t_row]      = pb0.w;
            Bs[t_col + 0][t_row + 64] = pb1.x;
            Bs[t_col + 1][t_row + 64] = pb1.y;
            Bs[t_col + 2][t_row + 64] = pb1.z;
            Bs[t_col + 3][t_row + 64] = pb1.w;
            __syncthreads();

            if (k0 + BK < KD) {
                const int kn = k0 + BK;
                pa0 = *(const float4*)(Ablk + (size_t)t_row        * KD + kn + t_col);
                pa1 = *(const float4*)(Ablk + (size_t)(t_row + 64) * KD + kn + t_col);
                pb0 = *(const float4*)(Bblk + (size_t)t_row        * KD + kn + t_col);
                pb1 = *(const float4*)(Bblk + (size_t)(t_row + 64) * KD + kn + t_col);
            }

#pragma unroll
            for (int kk = 0; kk < BK; kk++) {
                float a[8], b[8];
                *(float4*)&a[0] = *(const float4*)&As[kk][tm * 8];
                *(float4*)&a[4] = *(const float4*)&As[kk][tm * 8 + 4];
                *(float4*)&b[0] = *(const float4*)&Bs[kk][tn * 8];
                *(float4*)&b[4] = *(const float4*)&Bs[kk][tn * 8 + 4];
#pragma unroll
                for (int i = 0; i < 8; i++)
#pragma unroll
                    for (int j = 0; j < 8; j++) acc[i][j] += a[i] * b[j];
            }
        }
        __syncthreads();

        // per-thread argmin over its 8 columns; ascending j => first-min tiebreak
        float cn[8];
        *(float4*)&cn[0] = *(const float4*)&cnorm[j0 + tn * 8];
        *(float4*)&cn[4] = *(const float4*)&cnorm[j0 + tn * 8 + 4];
#pragma unroll
        for (int i = 0; i < 8; i++) {
            float mv = 3.4e38f; int mi = 0;
#pragma unroll
            for (int j = 0; j < 8; j++) {
                float s = cn[j] - 2.f * acc[i][j];
                if (s < mv) { mv = s; mi = j0 + tn * 8 + j; }
            }
            s_rv[tm * 8 + i][tn] = mv;
            s_ri[tm * 8 + i][tn] = mi;
        }
        __syncthreads();
        if (tid < BM) {
            float mv = s_bestv[tid]; int mi = s_besti[tid];
#pragma unroll
            for (int t = 0; t < 16; t++) {      // ascending j order
                float v = s_rv[tid][t];
                if (v < mv) { mv = v; mi = s_ri[tid][t]; }
            }
            s_bestv[tid] = mv; s_besti[tid] = mi;
        }
    }
    __syncthreads();
    if (tid < BM) {
        pval[(size_t)grp * NR + bm * BM + tid] = s_bestv[tid];
        pidx[(size_t)grp * NR + bm * BM + tid] = s_besti[tid];
    }
}

// ---------------- combine the 4 j-groups (ascending => first-min tiebreak) ---
__global__ void combine_kernel(const float* __restrict__ pval, const int* __restrict__ pidx,
                               const float* __restrict__ znorm,
                               float* __restrict__ minval, int* __restrict__ minidx)
{
    int r = blockIdx.x * blockDim.x + threadIdx.x;
    if (r >= NR) return;
    float mv = 3.4e38f; int mi = 0;
#pragma unroll
    for (int g = 0; g < 4; g++) {
        float v = pval[(size_t)g * NR + r];
        if (v < mv) { mv = v; mi = pidx[(size_t)g * NR + r]; }
    }
    minval[r] = znorm[r] + mv;
    minidx[r] = mi;
}

// ---------------- gather codebook rows into output ---------------------------
__global__ void gather_kernel(const float* __restrict__ CB, const int* __restrict__ minidx,
                              float* __restrict__ out)
{
    int r = blockIdx.x;
    int c = threadIdx.x;            // 64 threads * float4 = 256 floats
    float4 v = *(const float4*)&CB[(size_t)minidx[r] * DZ + c * 4];
    *(float4*)&out[(size_t)r * DZ + c * 4] = v;
}

// ---------------- deterministic loss reduction -------------------------------
__global__ void loss_kernel(const float* __restrict__ minval, float* __restrict__ out,
                            int out_size)
{
    __shared__ float sm[512];
    int t = threadIdx.x;
    float s = 0.f;
    for (int i = t; i < NR; i += 512) s += minval[i];   // fixed-order partials
    sm[t] = s;
    __syncthreads();
    for (int w = 256; w > 0; w >>= 1) {
        if (t < w) sm[t] += sm[t + w];
        __syncthreads();
    }
    if (t == 0 && out_size > NR * DZ) out[NR * DZ] = 2.f * sm[0];  // z_loss == c_loss
}

// ---------------- launch -----------------------------------------------------
extern "C" void kernel_launch(void* const* d_in, const int* in_sizes, int n_in,
                              void* d_out, int out_size)
{
    const float* x  = (const float*)d_in[0];
    const float* W1 = (const float*)d_in[1];
    const float* b1 = (const float*)d_in[2];
    const float* W2 = (const float*)d_in[3];
    const float* b2 = (const float*)d_in[4];
    const float* W3 = (const float*)d_in[5];
    const float* b3 = (const float*)d_in[6];
    const float* CB = (const float*)d_in[7];
    float* out = (float*)d_out;

    float *h1, *h2, *z, *znorm, *cnorm, *pval, *minval;
    int *pidx, *minidx;
    cudaGetSymbolAddress((void**)&h1,     g_h1);
    cudaGetSymbolAddress((void**)&h2,     g_h2);
    cudaGetSymbolAddress((void**)&z,      g_z);
    cudaGetSymbolAddress((void**)&znorm,  g_znorm);
    cudaGetSymbolAddress((void**)&cnorm,  g_cnorm);
    cudaGetSymbolAddress((void**)&pval,   g_pval);
    cudaGetSymbolAddress((void**)&pidx,   g_pidx);
    cudaGetSymbolAddress((void**)&minval, g_minval);
    cudaGetSymbolAddress((void**)&minidx, g_minidx);

    // MLP
    sgemm_bias_kernel<true ><<<dim3(DH / 128, NR / 128), 256>>>(x,  W1, b1, h1, NR, DH, DIN);
    sgemm_bias_kernel<false><<<dim3(DH / 128, NR / 128), 256>>>(h1, W2, b2, h2, NR, DH, DH);
    sgemm_bias_kernel<false><<<dim3(DZ / 128, NR / 128), 256>>>(h2, W3, b3, z,  NR, DZ, DH);

    // norms
    rownorm256_kernel<<<(KCB * 32) / 256, 256>>>(CB, cnorm, KCB);
    rownorm256_kernel<<<(NR  * 32) / 256, 256>>>(z,  znorm, NR);

    // fused distance + argmin
    distmin_kernel<<<dim3(4, NR / 128), 256>>>(z, CB, cnorm, pval, pidx);
    combine_kernel<<<NR / 256, 256>>>(pval, pidx, znorm, minval, minidx);

    // outputs
    gather_kernel<<<NR, 64>>>(CB, minidx, out);
    loss_kernel<<<1, 512>>>(minval, out, out_size);
}